// round 9
// baseline (speedup 1.0000x reference)
#include <cuda_runtime.h>
#include <cuda_bf16.h>

#define NN 512
#define BATCH 32
#define TT 4
#define NROWS (BATCH * TT)                        // 128
#define SRC_ELEMS ((size_t)BATCH * 2 * NN * NN)   // 16,777,216
#define TGT_ELEMS ((size_t)NROWS * NN)            // 65,536

// FFT results, SoA. 2 x 256 KB. Allocation-free scratch.
__device__ float g_Yr[NROWS][NN];
__device__ float g_Yi[NROWS][NN];

typedef unsigned long long u64;

// ---- packed f32x2 helpers ----
__device__ __forceinline__ u64 pk2(float lo, float hi) {
    u64 r; asm("mov.b64 %0, {%1, %2};" : "=l"(r) : "f"(lo), "f"(hi)); return r;
}
__device__ __forceinline__ void up2(u64 v, float& lo, float& hi) {
    asm("mov.b64 {%0, %1}, %2;" : "=f"(lo), "=f"(hi) : "l"(v));
}
__device__ __forceinline__ u64 f2mul(u64 a, u64 b) {
    u64 d; asm("mul.rn.f32x2 %0, %1, %2;" : "=l"(d) : "l"(a), "l"(b)); return d;
}
__device__ __forceinline__ u64 f2fma(u64 a, u64 b, u64 c) {
    u64 d; asm("fma.rn.f32x2 %0, %1, %2, %3;" : "=l"(d) : "l"(a), "l"(b), "l"(c)); return d;
}

#define SGNMASK 0x8000000080000000ULL

// ---------------------------------------------------------------------------
// Kernel 1: 512-pt DFT of real input, per row (b,t). (unchanged from R8)
// ---------------------------------------------------------------------------
__global__ __launch_bounds__(1024) void dft512_kernel(const float* __restrict__ x) {
    __shared__ float xs[NN];
    __shared__ float s[NN / 2];
    __shared__ float d[NN / 2];
    __shared__ float pRe[3][256];
    __shared__ float pIm[3][256];
    __shared__ float pAlt[4];

    const int row = blockIdx.x;
    const int tid = threadIdx.x;
    const int k   = tid & 255;
    const int q   = tid >> 8;

    if (tid < NN) xs[tid] = x[row * NN + tid];
    __syncthreads();
    if (tid >= 1 && tid < 256) {
        s[tid] = xs[tid] + xs[NN - tid];
        d[tid] = xs[tid] - xs[NN - tid];
    }
    __syncthreads();

    const float W = 6.283185307179586f / (float)NN;
    float s2, c2;
    sincosf(2.0f * W * (float)k, &s2, &c2);

    float re = 0.0f, im = 0.0f, alt = 0.0f;

#pragma unroll
    for (int c = 0; c < 2; ++c) {
        const int n0  = q * 64 + c * 32;
        const int phA = (k * n0) & (NN - 1);
        const int phB = (k * (n0 + 1)) & (NN - 1);
        float sA, cA, sB, cB;
        sincosf(W * (float)phA, &sA, &cA);
        sincosf(W * (float)phB, &sB, &cB);
#pragma unroll
        for (int j = 0; j < 16; ++j) {
            const int nA = n0 + 2 * j;
            const int nB = nA + 1;
            if (nA >= 1) {
                re  = fmaf(s[nA], cA, re);
                im  = fmaf(-d[nA], sA, im);
                alt += s[nA];
            }
            re  = fmaf(s[nB], cB, re);
            im  = fmaf(-d[nB], sB, im);
            alt -= s[nB];
            const float nrA = fmaf(cA, c2, -(sA * s2));
            sA = fmaf(cA, s2, sA * c2); cA = nrA;
            const float nrB = fmaf(cB, c2, -(sB * s2));
            sB = fmaf(cB, s2, sB * c2); cB = nrB;
        }
    }

    if (q > 0) {
        pRe[q - 1][k] = re;
        pIm[q - 1][k] = im;
        if (k == 0) pAlt[q] = alt;
    } else if (k == 0) {
        pAlt[0] = alt;
    }
    __syncthreads();

    if (q == 0) {
        re += pRe[0][k] + pRe[1][k] + pRe[2][k];
        im += pIm[0][k] + pIm[1][k] + pIm[2][k];
        const float x0 = xs[0], x256 = xs[NN / 2];
        re += x0 + ((k & 1) ? -x256 : x256);
        g_Yr[row][k] = re;
        g_Yi[row][k] = im;
        if (k == 0) {
            g_Yr[row][NN / 2] = x0 + x256 + pAlt[0] + pAlt[1] + pAlt[2] + pAlt[3];
            g_Yi[row][NN / 2] = 0.0f;
        } else {
            g_Yr[row][NN - k] = re;
            g_Yi[row][NN - k] = -im;
        }
    }
}

// ---------------------------------------------------------------------------
// Kernel 2: Bx[k,l] = y[k]*conj(y[l])*y[(l-k) mod N], averaged over T.
// Parity-split k-tile: thread handles k = k0 + 2a + p (p warp-uniform).
// All yc offsets for one thread share parity -> with a +1-shifted shadow
// copy in smem, every yc/yl pair is a naturally-aligned direct LDS.64
// (zero packing MOVs). Negations via XOR on packed regs. 3 CTAs/SM.
// ---------------------------------------------------------------------------
__global__ __launch_bounds__(256, 3) void bispec_kernel(float* __restrict__ out) {
    __shared__ float ysr [TT][NN];
    __shared__ float ysi [TT][NN];
    __shared__ float ysrs[TT][NN];   // ysrs[t][j] = ysr[t][(j+1) & 511]
    __shared__ float ysis[TT][NN];

    const int b    = blockIdx.y;     // 0..31
    const int kblk = blockIdx.x;     // 0..63

    {
        const float4* srcr = (const float4*)g_Yr[b * TT];
        const float4* srci = (const float4*)g_Yi[b * TT];
        const float*  scr  = (const float*)g_Yr[b * TT];
        const float*  sci  = (const float*)g_Yi[b * TT];
        float4* dr = (float4*)&ysr[0][0];
        float4* di = (float4*)&ysi[0][0];
        float* drs = &ysrs[0][0];
        float* dis = &ysis[0][0];
        for (int i = threadIdx.x; i < TT * NN / 4; i += 256) {
            dr[i] = srcr[i];
            di[i] = srci[i];
        }
        for (int i = threadIdx.x; i < TT * NN; i += 256) {
            const int t = i >> 9, j = i & (NN - 1);
            const int js = (t << 9) | ((j + 1) & (NN - 1));
            drs[i] = scr[js];
            dis[i] = sci[js];
        }
    }
    __syncthreads();

    const int lane  = threadIdx.x & 127;
    const int p     = threadIdx.x >> 7;      // warp-uniform parity
    const int k0    = kblk * 8;
    const int lbase = lane * 4;
    const int Abase = lbase - k0 - 6 - 2 * p + 2048;  // keep positive pre-mask

    // parity-selected source arrays for yc pairs
    const float (*Ycr)[NN] = p ? ysrs : ysr;
    const float (*Yci)[NN] = p ? ysis : ysi;

    u64 accr[4][2], acci[4][2];
#pragma unroll
    for (int a = 0; a < 4; ++a)
#pragma unroll
        for (int lp = 0; lp < 2; ++lp) { accr[a][lp] = 0ull; acci[a][lp] = 0ull; }

#pragma unroll
    for (int t = 0; t < TT; ++t) {
        // y[l] pairs: aligned direct LDS.64 (lbase is 4-elem aligned)
        const u64 ylr[2] = { *(const u64*)&ysr[t][lbase], *(const u64*)&ysr[t][lbase + 2] };
        const u64 yli[2] = { *(const u64*)&ysi[t][lbase], *(const u64*)&ysi[t][lbase + 2] };

        // yc pairs: 5 per component, all aligned LDS.64 from parity array
        u64 ycr[5], yci[5];
#pragma unroll
        for (int m = 0; m < 5; ++m) {
            const int A = (Abase + 2 * m) & (NN - 1);   // even
            ycr[m] = *(const u64*)&Ycr[t][A];
            yci[m] = *(const u64*)&Yci[t][A];
        }

#pragma unroll
        for (int a = 0; a < 4; ++a) {
            const int k = k0 + 2 * a + p;
            const float kr = ysr[t][k];                 // warp-uniform broadcast
            const float ki = ysi[t][k];
            const u64 ykr2  = pk2(kr, kr);
            const u64 yki2  = pk2(ki, ki);
            const u64 nykr2 = ykr2 ^ SGNMASK;
#pragma unroll
            for (int lp = 0; lp < 2; ++lp) {
                const int m = 3 + lp - a;               // 0..4, compile-time
                // a = y[k]*conj(y[l])
                const u64 ar2  = f2fma(yki2, yli[lp], f2mul(ykr2, ylr[lp]));
                const u64 ai2  = f2fma(nykr2, yli[lp], f2mul(yki2, ylr[lp]));
                const u64 nai2 = ai2 ^ SGNMASK;
                // Bx = a * yc
                accr[a][lp] = f2fma(ar2,  ycr[m], accr[a][lp]);
                accr[a][lp] = f2fma(nai2, yci[m], accr[a][lp]);
                acci[a][lp] = f2fma(ar2,  yci[m], acci[a][lp]);
                acci[a][lp] = f2fma(ai2,  ycr[m], acci[a][lp]);
            }
        }
    }

    float* outb = out + (size_t)b * 2 * NN * NN;
    const u64 quarter = pk2(0.25f, 0.25f);
#pragma unroll
    for (int a = 0; a < 4; ++a) {
        const int k = k0 + 2 * a + p;
        float r0, r1, r2, r3, i0, i1, i2, i3;
        up2(f2mul(accr[a][0], quarter), r0, r1);
        up2(f2mul(accr[a][1], quarter), r2, r3);
        up2(f2mul(acci[a][0], quarter), i0, i1);
        up2(f2mul(acci[a][1], quarter), i2, i3);
        *(float4*)&outb[(size_t)k * NN + lbase] = make_float4(r0, r1, r2, r3);
        *(float4*)&outb[(size_t)NN * NN + (size_t)k * NN + lbase] = make_float4(i0, i1, i2, i3);
    }
}

extern "C" void kernel_launch(void* const* d_in, const int* in_sizes, int n_in,
                              void* d_out, int out_size) {
    const float* target = (const float*)d_in[0];
    float* out = (float*)d_out;

    dft512_kernel<<<NROWS, 1024>>>(target);

    dim3 grid(NN / 8, BATCH);
    bispec_kernel<<<grid, 256>>>(out);

    if ((size_t)out_size >= SRC_ELEMS + TGT_ELEMS) {
        cudaMemcpyAsync(out + SRC_ELEMS, target, TGT_ELEMS * sizeof(float),
                        cudaMemcpyDeviceToDevice, 0);
    }
}

// round 15
// speedup vs baseline: 1.1386x; 1.1386x over previous
#include <cuda_runtime.h>
#include <cuda_bf16.h>

#define NN 512
#define BATCH 32
#define TT 4
#define NROWS (BATCH * TT)                        // 128
#define SRC_ELEMS ((size_t)BATCH * 2 * NN * NN)   // 16,777,216
#define TGT_ELEMS ((size_t)NROWS * NN)            // 65,536

// FFT results (pre-scaled by cbrt(0.25)), SoA. Allocation-free scratch.
__device__ float g_Yr[NROWS][NN];
__device__ float g_Yi[NROWS][NN];

typedef unsigned long long u64;

// ---- packed f32x2 helpers ----
__device__ __forceinline__ u64 pk2(float lo, float hi) {
    u64 r; asm("mov.b64 %0, {%1, %2};" : "=l"(r) : "f"(lo), "f"(hi)); return r;
}
__device__ __forceinline__ void up2(u64 v, float& lo, float& hi) {
    asm("mov.b64 {%0, %1}, %2;" : "=f"(lo), "=f"(hi) : "l"(v));
}
__device__ __forceinline__ u64 f2mul(u64 a, u64 b) {
    u64 d; asm("mul.rn.f32x2 %0, %1, %2;" : "=l"(d) : "l"(a), "l"(b)); return d;
}
__device__ __forceinline__ u64 f2fma(u64 a, u64 b, u64 c) {
    u64 d; asm("fma.rn.f32x2 %0, %1, %2, %3;" : "=l"(d) : "l"(a), "l"(b), "l"(c)); return d;
}

#define SGNMASK 0x8000000080000000ULL

// bank swizzle (BIJECTIVE): j -> j XOR (4 * ((j>>5)&1)).
// Per 32-float block, odd blocks flip bit 2. float4s at 4-aligned j keep
// contiguity (bits 0-1 untouched) and never leave their block (max o = 511).
__device__ __forceinline__ int swz(int j) { return j ^ ((j >> 3) & 4); }

// ---------------------------------------------------------------------------
// Kernel 1: 512-pt DFT of real input, per row (b,t).
// Output pre-scaled by cbrt(0.25): the bispectrum triple product then carries
// the 1/T = 0.25 averaging exactly (0.25 = cbrt(0.25)^3).
// ---------------------------------------------------------------------------
__global__ __launch_bounds__(1024) void dft512_kernel(const float* __restrict__ x) {
    __shared__ float xs[NN];
    __shared__ float s[NN / 2];
    __shared__ float d[NN / 2];
    __shared__ float pRe[3][256];
    __shared__ float pIm[3][256];
    __shared__ float pAlt[4];

    const int row = blockIdx.x;
    const int tid = threadIdx.x;
    const int k   = tid & 255;
    const int q   = tid >> 8;

    if (tid < NN) xs[tid] = x[row * NN + tid];
    __syncthreads();
    if (tid >= 1 && tid < 256) {
        s[tid] = xs[tid] + xs[NN - tid];
        d[tid] = xs[tid] - xs[NN - tid];
    }
    __syncthreads();

    const float W = 6.283185307179586f / (float)NN;
    float s2, c2;
    sincosf(2.0f * W * (float)k, &s2, &c2);

    float re = 0.0f, im = 0.0f, alt = 0.0f;

#pragma unroll
    for (int c = 0; c < 2; ++c) {
        const int n0  = q * 64 + c * 32;
        const int phA = (k * n0) & (NN - 1);
        const int phB = (k * (n0 + 1)) & (NN - 1);
        float sA, cA, sB, cB;
        sincosf(W * (float)phA, &sA, &cA);
        sincosf(W * (float)phB, &sB, &cB);
#pragma unroll
        for (int j = 0; j < 16; ++j) {
            const int nA = n0 + 2 * j;
            const int nB = nA + 1;
            if (nA >= 1) {
                re  = fmaf(s[nA], cA, re);
                im  = fmaf(-d[nA], sA, im);
                alt += s[nA];
            }
            re  = fmaf(s[nB], cB, re);
            im  = fmaf(-d[nB], sB, im);
            alt -= s[nB];
            const float nrA = fmaf(cA, c2, -(sA * s2));
            sA = fmaf(cA, s2, sA * c2); cA = nrA;
            const float nrB = fmaf(cB, c2, -(sB * s2));
            sB = fmaf(cB, s2, sB * c2); cB = nrB;
        }
    }

    if (q > 0) {
        pRe[q - 1][k] = re;
        pIm[q - 1][k] = im;
        if (k == 0) pAlt[q] = alt;
    } else if (k == 0) {
        pAlt[0] = alt;
    }
    __syncthreads();

    if (q == 0) {
        const float SC = 0.6299605249474366f;   // cbrt(0.25)
        re += pRe[0][k] + pRe[1][k] + pRe[2][k];
        im += pIm[0][k] + pIm[1][k] + pIm[2][k];
        const float x0 = xs[0], x256 = xs[NN / 2];
        re += x0 + ((k & 1) ? -x256 : x256);
        re *= SC;
        im *= SC;
        g_Yr[row][k] = re;
        g_Yi[row][k] = im;
        if (k == 0) {
            g_Yr[row][NN / 2] = SC * (x0 + x256 + pAlt[0] + pAlt[1] + pAlt[2] + pAlt[3]);
            g_Yi[row][NN / 2] = 0.0f;
        } else {
            g_Yr[row][NN - k] = re;
            g_Yi[row][NN - k] = -im;
        }
    }
}

// ---------------------------------------------------------------------------
// Kernel 2: Bx[k,l] = y[k]*conj(y[l])*y[(l-k) mod N], summed over T (avg is
// pre-folded into y). 256 thr = 4 ksub-groups x 64 l-lanes; thread tile
// 4k x 8l; block covers 16k x 512l. XOR bank swizzle makes the 32B-stride
// float4 loads conflict-free.
// ---------------------------------------------------------------------------
__global__ __launch_bounds__(256, 2) void bispec_kernel(float* __restrict__ out) {
    __shared__ float ysr[TT][NN];
    __shared__ float ysi[TT][NN];

    const int b    = blockIdx.y;     // 0..31
    const int kblk = blockIdx.x;     // 0..31 (16 k each)

    {
        const float4* srcr = (const float4*)g_Yr[b * TT];
        const float4* srci = (const float4*)g_Yi[b * TT];
        for (int i = threadIdx.x; i < TT * NN / 4; i += 256) {
            const int t = i >> 7;             // 128 float4 per row
            const int j = (i & 127) << 2;     // float index in row
            const int o = swz(j);
            *(float4*)&ysr[t][o] = srcr[i];
            *(float4*)&ysi[t][o] = srci[i];
        }
    }
    __syncthreads();

    const int lane64 = threadIdx.x & 63;
    const int ksub   = threadIdx.x >> 6;       // warp-uniform
    const int k0     = kblk * 16 + ksub * 4;   // 4 consecutive k
    const int lbase  = lane64 * 8;             // 8 consecutive l

    u64 accr[4][4], acci[4][4];                // [ka][lpair]
#pragma unroll
    for (int a = 0; a < 4; ++a)
#pragma unroll
        for (int p = 0; p < 4; ++p) { accr[a][p] = 0ull; acci[a][p] = 0ull; }

#pragma unroll 1
    for (int t = 0; t < TT; ++t) {
        // y[l]: 8 consecutive floats, 2 float4 per component (swizzled, CF)
        const float4 l0r = *(const float4*)&ysr[t][swz(lbase)];
        const float4 l1r = *(const float4*)&ysr[t][swz(lbase + 4)];
        const float4 l0i = *(const float4*)&ysi[t][swz(lbase)];
        const float4 l1i = *(const float4*)&ysi[t][swz(lbase + 4)];
        const u64 ylr[4] = { pk2(l0r.x,l0r.y), pk2(l0r.z,l0r.w),
                             pk2(l1r.x,l1r.y), pk2(l1r.z,l1r.w) };
        const u64 yli[4] = { pk2(l0i.x,l0i.y), pk2(l0i.z,l0i.w),
                             pk2(l1i.x,l1i.y), pk2(l1i.z,l1i.w) };

        // yc window: 12 consecutive values starting at lbase-k0-4 (mod 512)
        const int base = (lbase - k0 - 4 + 1024) & (NN - 1);
        const int A0 = swz(base);
        const int A1 = swz((base + 4) & (NN - 1));
        const int A2 = swz((base + 8) & (NN - 1));
        const float4 c0r = *(const float4*)&ysr[t][A0];
        const float4 c1r = *(const float4*)&ysr[t][A1];
        const float4 c2r = *(const float4*)&ysr[t][A2];
        const float4 c0i = *(const float4*)&ysi[t][A0];
        const float4 c1i = *(const float4*)&ysi[t][A1];
        const float4 c2i = *(const float4*)&ysi[t][A2];
        // even-offset pairs (offsets 0,2,4,6,8,10)
        const u64 evr[6] = { pk2(c0r.x,c0r.y), pk2(c0r.z,c0r.w),
                             pk2(c1r.x,c1r.y), pk2(c1r.z,c1r.w),
                             pk2(c2r.x,c2r.y), pk2(c2r.z,c2r.w) };
        const u64 evi[6] = { pk2(c0i.x,c0i.y), pk2(c0i.z,c0i.w),
                             pk2(c1i.x,c1i.y), pk2(c1i.z,c1i.w),
                             pk2(c2i.x,c2i.y), pk2(c2i.z,c2i.w) };
        // odd-offset pairs (offsets 1,3,5,7,9)
        const u64 odr[5] = { pk2(c0r.y,c0r.z), pk2(c0r.w,c1r.x),
                             pk2(c1r.y,c1r.z), pk2(c1r.w,c2r.x),
                             pk2(c2r.y,c2r.z) };
        const u64 odi[5] = { pk2(c0i.y,c0i.z), pk2(c0i.w,c1i.x),
                             pk2(c1i.y,c1i.z), pk2(c1i.w,c2i.x),
                             pk2(c2i.y,c2i.z) };

        // y[k]: one broadcast float4 per component (k0 4-aligned, warp-uniform)
        const float4 kr4 = *(const float4*)&ysr[t][swz(k0)];
        const float4 ki4 = *(const float4*)&ysi[t][swz(k0)];
        const float krA[4] = { kr4.x, kr4.y, kr4.z, kr4.w };
        const float kiA[4] = { ki4.x, ki4.y, ki4.z, ki4.w };

#pragma unroll
        for (int ka = 0; ka < 4; ++ka) {
            const u64 ykr2  = pk2(krA[ka], krA[ka]);
            const u64 yki2  = pk2(kiA[ka], kiA[ka]);
            const u64 nykr2 = ykr2 ^ SGNMASK;
#pragma unroll
            for (int lp = 0; lp < 4; ++lp) {
                const int o = 4 + 2 * lp - ka;          // 1..10, compile-time
                const u64 ycr2 = (o & 1) ? odr[(o - 1) >> 1] : evr[o >> 1];
                const u64 yci2 = (o & 1) ? odi[(o - 1) >> 1] : evi[o >> 1];
                // a = y[k]*conj(y[l])
                const u64 ar2  = f2fma(yki2, yli[lp], f2mul(ykr2, ylr[lp]));
                const u64 ai2  = f2fma(nykr2, yli[lp], f2mul(yki2, ylr[lp]));
                const u64 nai2 = ai2 ^ SGNMASK;
                // Bx = a * yc  (0.25 pre-folded into y)
                accr[ka][lp] = f2fma(ar2,  ycr2, accr[ka][lp]);
                accr[ka][lp] = f2fma(nai2, yci2, accr[ka][lp]);
                acci[ka][lp] = f2fma(ar2,  yci2, acci[ka][lp]);
                acci[ka][lp] = f2fma(ai2,  ycr2, acci[ka][lp]);
            }
        }
    }

    float* outb = out + (size_t)b * 2 * NN * NN;
#pragma unroll
    for (int ka = 0; ka < 4; ++ka) {
        const int k = k0 + ka;
        float r0,r1,r2,r3,r4,r5,r6,r7, i0,i1,i2,i3,i4,i5,i6,i7;
        up2(accr[ka][0], r0, r1); up2(accr[ka][1], r2, r3);
        up2(accr[ka][2], r4, r5); up2(accr[ka][3], r6, r7);
        up2(acci[ka][0], i0, i1); up2(acci[ka][1], i2, i3);
        up2(acci[ka][2], i4, i5); up2(acci[ka][3], i6, i7);
        float* rowr = outb + (size_t)k * NN + lbase;
        float* rowi = rowr + (size_t)NN * NN;
        *(float4*)(rowr)     = make_float4(r0, r1, r2, r3);
        *(float4*)(rowr + 4) = make_float4(r4, r5, r6, r7);
        *(float4*)(rowi)     = make_float4(i0, i1, i2, i3);
        *(float4*)(rowi + 4) = make_float4(i4, i5, i6, i7);
    }
}

extern "C" void kernel_launch(void* const* d_in, const int* in_sizes, int n_in,
                              void* d_out, int out_size) {
    const float* target = (const float*)d_in[0];
    float* out = (float*)d_out;

    dft512_kernel<<<NROWS, 1024>>>(target);

    dim3 grid(NN / 16, BATCH);
    bispec_kernel<<<grid, 256>>>(out);

    if ((size_t)out_size >= SRC_ELEMS + TGT_ELEMS) {
        cudaMemcpyAsync(out + SRC_ELEMS, target, TGT_ELEMS * sizeof(float),
                        cudaMemcpyDeviceToDevice, 0);
    }
}